// round 3
// baseline (speedup 1.0000x reference)
#include <cuda_runtime.h>
#include <cuda_bf16.h>
#include <math.h>

// Problem constants
#define B_   4
#define S_   2048
#define D_   1024
#define H_   16
#define DK_  64
#define NEG_ (-1000000000.0f)
#define SCALE_ (0.125f)   // 1/sqrt(64)

typedef unsigned long long u64;

// Packed fp32x2 FMA (Blackwell sm_103a): 2 IEEE fp32 FMAs per instruction.
__device__ __forceinline__ u64 ffma2(u64 a, u64 b, u64 c) {
    u64 d;
    asm("fma.rn.f32x2 %0, %1, %2, %3;" : "=l"(d) : "l"(a), "l"(b), "l"(c));
    return d;
}
__device__ __forceinline__ u64 pack2(float lo, float hi) {
    u64 d;
    asm("mov.b64 %0, {%1, %2};" : "=l"(d) : "f"(lo), "f"(hi));
    return d;
}
__device__ __forceinline__ float2 unpack2(u64 v) {
    float2 r;
    asm("mov.b64 {%0, %1}, %2;" : "=f"(r.x), "=f"(r.y) : "l"(v));
    return r;
}

// Scratch (allocation-free: __device__ globals), head-major [B, H, S, DK]
__device__ float g_qh[(size_t)B_ * H_ * S_ * DK_];
__device__ float g_kh[(size_t)B_ * H_ * S_ * DK_];
__device__ float g_vh[(size_t)B_ * H_ * S_ * DK_];
__device__ float g_ho[(size_t)B_ * H_ * S_ * DK_];

// Tiled GEMM: 128x64 C tile, K-step 16, 256 threads.
// Per-thread micro-tile: 8 rows x 4 cols, computed as 4 M-pairs via f32x2.
#define BM 128
#define BN 64
#define BK 16
#define BMP (BM + 4)   // row stride in floats; 132*4=528 bytes, 16B-aligned

// Inner product over one smem tile: acc[p][j] += A-pair(p) * B(j), packed.
#define MICRO_KERNEL()                                                        \
    _Pragma("unroll")                                                         \
    for (int kk = 0; kk < BK; kk++) {                                         \
        ulonglong2 aA = *(const ulonglong2*)&As[kk][ty * 8];                  \
        ulonglong2 aB = *(const ulonglong2*)&As[kk][ty * 8 + 4];              \
        ulonglong2 bA = *(const ulonglong2*)&Bs2[kk][tx * 4];                 \
        ulonglong2 bB = *(const ulonglong2*)&Bs2[kk][tx * 4 + 2];             \
        acc[0][0] = ffma2(aA.x, bA.x, acc[0][0]);                             \
        acc[0][1] = ffma2(aA.x, bA.y, acc[0][1]);                             \
        acc[0][2] = ffma2(aA.x, bB.x, acc[0][2]);                             \
        acc[0][3] = ffma2(aA.x, bB.y, acc[0][3]);                             \
        acc[1][0] = ffma2(aA.y, bA.x, acc[1][0]);                             \
        acc[1][1] = ffma2(aA.y, bA.y, acc[1][1]);                             \
        acc[1][2] = ffma2(aA.y, bB.x, acc[1][2]);                             \
        acc[1][3] = ffma2(aA.y, bB.y, acc[1][3]);                             \
        acc[2][0] = ffma2(aB.x, bA.x, acc[2][0]);                             \
        acc[2][1] = ffma2(aB.x, bA.y, acc[2][1]);                             \
        acc[2][2] = ffma2(aB.x, bB.x, acc[2][2]);                             \
        acc[2][3] = ffma2(aB.x, bB.y, acc[2][3]);                             \
        acc[3][0] = ffma2(aB.y, bA.x, acc[3][0]);                             \
        acc[3][1] = ffma2(aB.y, bA.y, acc[3][1]);                             \
        acc[3][2] = ffma2(aB.y, bB.x, acc[3][2]);                             \
        acc[3][3] = ffma2(aB.y, bB.y, acc[3][3]);                             \
    }

// ---------------------------------------------------------------------------
// Kernel 1: QKV projections. out[b,h,s,d] = x[b,s,:] . w[h*64+d,:] + bias
// grid: (16, 64, 3), 256 threads
// ---------------------------------------------------------------------------
__global__ __launch_bounds__(256)
void proj_qkv_kernel(const float* __restrict__ q, const float* __restrict__ k,
                     const float* __restrict__ v,
                     const float* __restrict__ wq, const float* __restrict__ bq,
                     const float* __restrict__ wk, const float* __restrict__ bk,
                     const float* __restrict__ wv, const float* __restrict__ bv)
{
    const float *X, *W, *bias;
    float* out;
    if (blockIdx.z == 0)      { X = q; W = wq; bias = bq; out = g_qh; }
    else if (blockIdx.z == 1) { X = k; W = wk; bias = bk; out = g_kh; }
    else                      { X = v; W = wv; bias = bv; out = g_vh; }

    __shared__ __align__(16) float As[BK][BMP];
    __shared__ __align__(16) u64   Bs2[BK][BN];

    const int tid = threadIdx.x;
    const int tx = tid & 15, ty = tid >> 4;
    const int m0 = blockIdx.y * BM;
    const int n0 = blockIdx.x * BN;

    const int alm = tid >> 1;            // 0..127
    const int alk = (tid & 1) << 3;      // 0 or 8
    const int blm = tid >> 2;            // 0..63
    const int blk = (tid & 3) << 2;      // 0,4,8,12

    u64 acc[4][4] = {};

    for (int k0 = 0; k0 < D_; k0 += BK) {
        {
            const float* ap = X + (size_t)(m0 + alm) * D_ + k0 + alk;
            float4 a0 = *(const float4*)(ap);
            float4 a1 = *(const float4*)(ap + 4);
            As[alk + 0][alm] = a0.x; As[alk + 1][alm] = a0.y;
            As[alk + 2][alm] = a0.z; As[alk + 3][alm] = a0.w;
            As[alk + 4][alm] = a1.x; As[alk + 5][alm] = a1.y;
            As[alk + 6][alm] = a1.z; As[alk + 7][alm] = a1.w;
        }
        {
            float4 b4 = *(const float4*)(W + (size_t)(n0 + blm) * D_ + k0 + blk);
            Bs2[blk + 0][blm] = pack2(b4.x, b4.x);
            Bs2[blk + 1][blm] = pack2(b4.y, b4.y);
            Bs2[blk + 2][blm] = pack2(b4.z, b4.z);
            Bs2[blk + 3][blm] = pack2(b4.w, b4.w);
        }
        __syncthreads();
        MICRO_KERNEL();
        __syncthreads();
    }

    const int n = n0 + tx * 4;
    const int h = n >> 6, d = n & 63;
    float4 bia = *(const float4*)(bias + n);
    #pragma unroll
    for (int p = 0; p < 4; p++) {
        float2 c0 = unpack2(acc[p][0]);
        float2 c1 = unpack2(acc[p][1]);
        float2 c2 = unpack2(acc[p][2]);
        float2 c3 = unpack2(acc[p][3]);
        int me = m0 + ty * 8 + 2 * p;
        int be = me >> 11, se = me & (S_ - 1);
        *(float4*)(out + ((((size_t)be * H_ + h) * S_ + se) * DK_) + d) =
            make_float4(c0.x + bia.x, c1.x + bia.y, c2.x + bia.z, c3.x + bia.w);
        int mo = me + 1;
        int bo2 = mo >> 11, so = mo & (S_ - 1);
        *(float4*)(out + ((((size_t)bo2 * H_ + h) * S_ + so) * DK_) + d) =
            make_float4(c0.y + bia.x, c1.y + bia.y, c2.y + bia.z, c3.y + bia.w);
    }
}

// ---------------------------------------------------------------------------
// Kernel 2: scores = Q K^T * scale, masked. per (b,h): [2048,2048]
// grid: (32, 16, 64)
// ---------------------------------------------------------------------------
__global__ __launch_bounds__(256)
void scores_kernel(const int* __restrict__ mask, float* __restrict__ attn)
{
    const int z = blockIdx.z;
    const int b = z >> 4;
    const float* Q  = g_qh + (size_t)z * S_ * DK_;
    const float* Km = g_kh + (size_t)z * S_ * DK_;
    const int* mbase = mask + (size_t)b * S_ * S_;
    float* out = attn + (size_t)z * S_ * S_;

    __shared__ __align__(16) float As[BK][BMP];
    __shared__ __align__(16) u64   Bs2[BK][BN];

    const int tid = threadIdx.x;
    const int tx = tid & 15, ty = tid >> 4;
    const int m0 = blockIdx.y * BM;
    const int n0 = blockIdx.x * BN;

    const int alm = tid >> 1;
    const int alk = (tid & 1) << 3;
    const int blm = tid >> 2;
    const int blk = (tid & 3) << 2;

    u64 acc[4][4] = {};

    for (int k0 = 0; k0 < DK_; k0 += BK) {
        {
            const float* ap = Q + (size_t)(m0 + alm) * DK_ + k0 + alk;
            float4 a0 = *(const float4*)(ap);
            float4 a1 = *(const float4*)(ap + 4);
            As[alk + 0][alm] = a0.x; As[alk + 1][alm] = a0.y;
            As[alk + 2][alm] = a0.z; As[alk + 3][alm] = a0.w;
            As[alk + 4][alm] = a1.x; As[alk + 5][alm] = a1.y;
            As[alk + 6][alm] = a1.z; As[alk + 7][alm] = a1.w;
        }
        {
            float4 b4 = *(const float4*)(Km + (size_t)(n0 + blm) * DK_ + k0 + blk);
            Bs2[blk + 0][blm] = pack2(b4.x, b4.x);
            Bs2[blk + 1][blm] = pack2(b4.y, b4.y);
            Bs2[blk + 2][blm] = pack2(b4.z, b4.z);
            Bs2[blk + 3][blm] = pack2(b4.w, b4.w);
        }
        __syncthreads();
        MICRO_KERNEL();
        __syncthreads();
    }

    const int n = n0 + tx * 4;
    #pragma unroll
    for (int p = 0; p < 4; p++) {
        float2 c0 = unpack2(acc[p][0]);
        float2 c1 = unpack2(acc[p][1]);
        float2 c2 = unpack2(acc[p][2]);
        float2 c3 = unpack2(acc[p][3]);
        int me = m0 + ty * 8 + 2 * p;
        {
            int4 mm = *(const int4*)(mbase + (size_t)me * S_ + n);
            float4 r;
            r.x = (mm.x == 0) ? NEG_ : c0.x * SCALE_;
            r.y = (mm.y == 0) ? NEG_ : c1.x * SCALE_;
            r.z = (mm.z == 0) ? NEG_ : c2.x * SCALE_;
            r.w = (mm.w == 0) ? NEG_ : c3.x * SCALE_;
            *(float4*)(out + (size_t)me * S_ + n) = r;
        }
        int mo = me + 1;
        {
            int4 mm = *(const int4*)(mbase + (size_t)mo * S_ + n);
            float4 r;
            r.x = (mm.x == 0) ? NEG_ : c0.y * SCALE_;
            r.y = (mm.y == 0) ? NEG_ : c1.y * SCALE_;
            r.z = (mm.z == 0) ? NEG_ : c2.y * SCALE_;
            r.w = (mm.w == 0) ? NEG_ : c3.y * SCALE_;
            *(float4*)(out + (size_t)mo * S_ + n) = r;
        }
    }
}

// ---------------------------------------------------------------------------
// Kernel 3: in-place row softmax over 2048 elements. 1 block / row, 256 thr.
// ---------------------------------------------------------------------------
__global__ __launch_bounds__(256)
void softmax_kernel(float* __restrict__ attn)
{
    float* p = attn + (size_t)blockIdx.x * S_;
    const int t = threadIdx.x;
    const int lane = t & 31, warp = t >> 5;
    __shared__ float red[8];

    float4 v0 = *(const float4*)(p + t * 8);
    float4 v1 = *(const float4*)(p + t * 8 + 4);

    float mx = fmaxf(fmaxf(fmaxf(v0.x, v0.y), fmaxf(v0.z, v0.w)),
                     fmaxf(fmaxf(v1.x, v1.y), fmaxf(v1.z, v1.w)));
    #pragma unroll
    for (int off = 16; off > 0; off >>= 1)
        mx = fmaxf(mx, __shfl_xor_sync(0xffffffffu, mx, off));
    if (lane == 0) red[warp] = mx;
    __syncthreads();
    float gmx = red[0];
    #pragma unroll
    for (int w = 1; w < 8; w++) gmx = fmaxf(gmx, red[w]);
    __syncthreads();

    v0.x = __expf(v0.x - gmx); v0.y = __expf(v0.y - gmx);
    v0.z = __expf(v0.z - gmx); v0.w = __expf(v0.w - gmx);
    v1.x = __expf(v1.x - gmx); v1.y = __expf(v1.y - gmx);
    v1.z = __expf(v1.z - gmx); v1.w = __expf(v1.w - gmx);

    float s = (v0.x + v0.y + v0.z + v0.w) + (v1.x + v1.y + v1.z + v1.w);
    #pragma unroll
    for (int off = 16; off > 0; off >>= 1)
        s += __shfl_xor_sync(0xffffffffu, s, off);
    if (lane == 0) red[warp] = s;
    __syncthreads();
    float gs = red[0];
    #pragma unroll
    for (int w = 1; w < 8; w++) gs += red[w];
    const float inv = 1.0f / gs;

    v0.x *= inv; v0.y *= inv; v0.z *= inv; v0.w *= inv;
    v1.x *= inv; v1.y *= inv; v1.z *= inv; v1.w *= inv;
    *(float4*)(p + t * 8)     = v0;
    *(float4*)(p + t * 8 + 4) = v1;
}

// ---------------------------------------------------------------------------
// Kernel 4: PV GEMM. per (b,h): [2048,2048] @ [2048,64] -> [2048,64]
// grid: (1, 16, 64)
// ---------------------------------------------------------------------------
__global__ __launch_bounds__(256)
void pv_kernel(const float* __restrict__ attn)
{
    const int z = blockIdx.z;
    const float* A = attn + (size_t)z * S_ * S_;
    const float* V = g_vh + (size_t)z * S_ * DK_;
    float* out = g_ho + (size_t)z * S_ * DK_;

    __shared__ __align__(16) float As[BK][BMP];
    __shared__ __align__(16) u64   Bs2[BK][BN];

    const int tid = threadIdx.x;
    const int tx = tid & 15, ty = tid >> 4;
    const int m0 = blockIdx.y * BM;

    const int alm = tid >> 1;
    const int alk = (tid & 1) << 3;
    const int bkk = tid >> 4;            // 0..15
    const int bn4 = (tid & 15) << 2;     // 0..60

    u64 acc[4][4] = {};

    for (int k0 = 0; k0 < S_; k0 += BK) {
        {
            const float* ap = A + (size_t)(m0 + alm) * S_ + k0 + alk;
            float4 a0 = *(const float4*)(ap);
            float4 a1 = *(const float4*)(ap + 4);
            As[alk + 0][alm] = a0.x; As[alk + 1][alm] = a0.y;
            As[alk + 2][alm] = a0.z; As[alk + 3][alm] = a0.w;
            As[alk + 4][alm] = a1.x; As[alk + 5][alm] = a1.y;
            As[alk + 6][alm] = a1.z; As[alk + 7][alm] = a1.w;
        }
        {
            float4 b4 = *(const float4*)(V + (size_t)(k0 + bkk) * DK_ + bn4);
            Bs2[bkk][bn4 + 0] = pack2(b4.x, b4.x);
            Bs2[bkk][bn4 + 1] = pack2(b4.y, b4.y);
            Bs2[bkk][bn4 + 2] = pack2(b4.z, b4.z);
            Bs2[bkk][bn4 + 3] = pack2(b4.w, b4.w);
        }
        __syncthreads();
        MICRO_KERNEL();
        __syncthreads();
    }

    #pragma unroll
    for (int p = 0; p < 4; p++) {
        float2 c0 = unpack2(acc[p][0]);
        float2 c1 = unpack2(acc[p][1]);
        float2 c2 = unpack2(acc[p][2]);
        float2 c3 = unpack2(acc[p][3]);
        int me = m0 + ty * 8 + 2 * p;
        *(float4*)(out + (size_t)me * DK_ + tx * 4) =
            make_float4(c0.x, c1.x, c2.x, c3.x);
        *(float4*)(out + (size_t)(me + 1) * DK_ + tx * 4) =
            make_float4(c0.y, c1.y, c2.y, c3.y);
    }
}

// ---------------------------------------------------------------------------
// Kernel 5: output projection. output[b,s,o] = combined[b,s,:] . wo[o,:] + bo
// combined[b,s,k] = g_ho[b][k/64][s][k%64]
// grid: (16, 64)
// ---------------------------------------------------------------------------
__global__ __launch_bounds__(256)
void outproj_kernel(const float* __restrict__ wo, const float* __restrict__ bo,
                    float* __restrict__ outp)
{
    __shared__ __align__(16) float As[BK][BMP];
    __shared__ __align__(16) u64   Bs2[BK][BN];

    const int tid = threadIdx.x;
    const int tx = tid & 15, ty = tid >> 4;
    const int m0 = blockIdx.y * BM;
    const int n0 = blockIdx.x * BN;

    const int alm = tid >> 1;
    const int alk = (tid & 1) << 3;
    const int blm = tid >> 2;
    const int blk = (tid & 3) << 2;

    u64 acc[4][4] = {};

    for (int k0 = 0; k0 < D_; k0 += BK) {
        {
            int m = m0 + alm;
            int b = m >> 11, s = m & (S_ - 1);
            int kg = k0 + alk;                 // 8-aligned; stays in one 64-chunk
            int h = kg >> 6, d0 = kg & 63;
            const float* src = g_ho + ((((size_t)b * H_ + h) * S_ + s) * DK_) + d0;
            float4 a0 = *(const float4*)(src);
            float4 a1 = *(const float4*)(src + 4);
            As[alk + 0][alm] = a0.x; As[alk + 1][alm] = a0.y;
            As[alk + 2][alm] = a0.z; As[alk + 3][alm] = a0.w;
            As[alk + 4][alm] = a1.x; As[alk + 5][alm] = a1.y;
            As[alk + 6][alm] = a1.z; As[alk + 7][alm] = a1.w;
        }
        {
            float4 b4 = *(const float4*)(wo + (size_t)(n0 + blm) * D_ + k0 + blk);
            Bs2[blk + 0][blm] = pack2(b4.x, b4.x);
            Bs2[blk + 1][blm] = pack2(b4.y, b4.y);
            Bs2[blk + 2][blm] = pack2(b4.z, b4.z);
            Bs2[blk + 3][blm] = pack2(b4.w, b4.w);
        }
        __syncthreads();
        MICRO_KERNEL();
        __syncthreads();
    }

    const int n = n0 + tx * 4;
    float4 bia = *(const float4*)(bo + n);
    #pragma unroll
    for (int p = 0; p < 4; p++) {
        float2 c0 = unpack2(acc[p][0]);
        float2 c1 = unpack2(acc[p][1]);
        float2 c2 = unpack2(acc[p][2]);
        float2 c3 = unpack2(acc[p][3]);
        int me = m0 + ty * 8 + 2 * p;
        *(float4*)(outp + (size_t)me * D_ + n) =
            make_float4(c0.x + bia.x, c1.x + bia.y, c2.x + bia.z, c3.x + bia.w);
        *(float4*)(outp + (size_t)(me + 1) * D_ + n) =
            make_float4(c0.y + bia.x, c1.y + bia.y, c2.y + bia.z, c3.y + bia.w);
    }
}

// ---------------------------------------------------------------------------
// kernel_launch — input order: q k v mask wq bq wk bk wv bv wo bo
// output layout: [ output (B*S*D) | attn (B*H*S*S) ]
// ---------------------------------------------------------------------------
extern "C" void kernel_launch(void* const* d_in, const int* in_sizes, int n_in,
                              void* d_out, int out_size)
{
    const float* q    = (const float*)d_in[0];
    const float* k    = (const float*)d_in[1];
    const float* v    = (const float*)d_in[2];
    const int*   mask = (const int*)  d_in[3];
    const float* wq   = (const float*)d_in[4];
    const float* bq   = (const float*)d_in[5];
    const float* wk   = (const float*)d_in[6];
    const float* bk   = (const float*)d_in[7];
    const float* wv   = (const float*)d_in[8];
    const float* bv   = (const float*)d_in[9];
    const float* wo   = (const float*)d_in[10];
    const float* bo   = (const float*)d_in[11];

    float* outp = (float*)d_out;
    float* attn = outp + (size_t)B_ * S_ * D_;

    proj_qkv_kernel<<<dim3(D_ / BN, (B_ * S_) / BM, 3), 256>>>(
        q, k, v, wq, bq, wk, bk, wv, bv);

    scores_kernel<<<dim3(S_ / BN, S_ / BM, B_ * H_), 256>>>(mask, attn);

    softmax_kernel<<<B_ * H_ * S_, 256>>>(attn);

    pv_kernel<<<dim3(1, S_ / BM, B_ * H_), 256>>>(attn);

    outproj_kernel<<<dim3(D_ / BN, (B_ * S_) / BM), 256>>>(wo, bo, outp);
}